// round 10
// baseline (speedup 1.0000x reference)
#include <cuda_runtime.h>
#include <cuda_fp16.h>
#include <float.h>
#include <stdint.h>

#define Bb 4
#define Cc 256
#define C8 32
#define Hh 64
#define Ww 64
#define HW 4096

// ===================== helpers =============================================
__device__ __forceinline__ uint32_t smem_u32(const void* p) {
    uint32_t a;
    asm("{ .reg .u64 t; cvta.to.shared.u64 t, %1; cvt.u32.u64 %0, t; }"
        : "=r"(a) : "l"(p));
    return a;
}
#define SWZ128(off) ((off) ^ (((off) >> 3) & 0x70))

__device__ __forceinline__ void ldsm_x4(uint32_t (&r)[4], uint32_t addr) {
    asm volatile("ldmatrix.sync.aligned.m8n8.x4.shared.b16 {%0,%1,%2,%3}, [%4];"
                 : "=r"(r[0]), "=r"(r[1]), "=r"(r[2]), "=r"(r[3]) : "r"(addr));
}

__device__ __forceinline__ void mma_f16(float (&d)[4], const uint32_t (&a)[4],
                                        uint32_t b0, uint32_t b1) {
    asm volatile(
        "mma.sync.aligned.m16n8k16.row.col.f32.f16.f16.f32 "
        "{%0,%1,%2,%3}, {%4,%5,%6,%7}, {%8,%9}, {%0,%1,%2,%3};"
        : "+f"(d[0]), "+f"(d[1]), "+f"(d[2]), "+f"(d[3])
        : "r"(a[0]), "r"(a[1]), "r"(a[2]), "r"(a[3]), "r"(b0), "r"(b1));
}

#define CP_ASYNC16(dst, src) \
    asm volatile("cp.async.cg.shared.global [%0], [%1], 16;" :: "r"(dst), "l"(src) : "memory")
#define CP_COMMIT()  asm volatile("cp.async.commit_group;" ::: "memory")
#define CP_WAIT2()   asm volatile("cp.async.wait_group 2;" ::: "memory")
#define CP_WAIT1()   asm volatile("cp.async.wait_group 1;" ::: "memory")
#define CP_WAIT0()   asm volatile("cp.async.wait_group 0;" ::: "memory")

__device__ __forceinline__ uint32_t pack_h2(float a, float b) {
    __half2 h = __floats2half2_rn(a, b);
    return *(uint32_t*)&h;
}

// ===================== scratch =============================================
__device__ float g_q[Bb * C8 * HW];            // exact fp32 [b][c][hw]
__device__ float g_k[Bb * C8 * HW];
__device__ float g_vt[Bb * HW * Cc];           // NHWC value: [b][p][c]
__device__ float g_S[Bb * HW];
__device__ int   g_arg[Bb * HW];
__device__ int   g_flag[Bb * HW];
// fp16 q/k tiles, PRE-SWIZZLED: per 128-hw tile 8KB, addr SWZ128(local*64+seg*16)
__device__ __half g_qf[Bb * HW * 32];
__device__ __half g_kh2[Bb * HW * 32];
__device__ __half g_kl2[Bb * HW * 32];
// NHWC fp16 single plane, zero halo (device globals zero-init; halo never written)
__device__ __half g_Xt[(size_t)Bb * 66 * 66 * 512];
// conv weights split fp16: [seg(hi0/lo1)][tap9][o 256][c 512]
__device__ __half g_Wa[2 * 9 * 256 * 512];
// v weights split fp16: [o 256][c 256]
__device__ __half g_Wvh[256 * 256];
__device__ __half g_Wvl[256 * 256];

// ===================== fused q+k projection =================================
// exact fp32 [c][hw] + swizzled fp16 tiles (q single, k hi/lo)
__global__ __launch_bounds__(256) void gemm_qk(const float* __restrict__ cross_x,
                                               const float* __restrict__ front_x,
                                               const float* __restrict__ Wq,
                                               const float* __restrict__ bq,
                                               const float* __restrict__ Wk,
                                               const float* __restrict__ bk) {
    __shared__ float Xs[16][128];
    __shared__ float Ws[16][36];
    __shared__ float Ts[128][33];
    const int b   = blockIdx.z;
    const int sel = blockIdx.y;                 // 0 -> q, 1 -> k
    const int hw0 = blockIdx.x * 128;
    const int tid = threadIdx.x;
    const int hid = tid & 31;
    const int oid = tid >> 5;

    const float* X    = sel ? front_x : cross_x;
    const float* Wm   = sel ? Wk : Wq;
    const float* bias = sel ? bk : bq;
    float*       out  = sel ? g_k : g_q;

    const float* xb = X + (size_t)b * Cc * HW;
    float acc[4][4];
#pragma unroll
    for (int n = 0; n < 4; n++)
#pragma unroll
        for (int m = 0; m < 4; m++) acc[n][m] = 0.f;

    for (int c0 = 0; c0 < Cc; c0 += 16) {
        __syncthreads();
#pragma unroll
        for (int r = 0; r < 8; r++) {
            int idx = tid + r * 256;
            int cc = idx >> 7, h = idx & 127;
            Xs[cc][h] = xb[(size_t)(c0 + cc) * HW + hw0 + h];
        }
#pragma unroll
        for (int r = 0; r < 2; r++) {
            int idx = tid + r * 256;
            int cc = idx >> 5, o = idx & 31;
            Ws[cc][o] = Wm[(size_t)o * Cc + c0 + cc];
        }
        __syncthreads();
#pragma unroll
        for (int cc = 0; cc < 16; cc++) {
            float4 wv = *(const float4*)&Ws[cc][oid * 4];
            float4 xv = *(const float4*)&Xs[cc][hid * 4];
            float wa[4] = {wv.x, wv.y, wv.z, wv.w};
            float xa[4] = {xv.x, xv.y, xv.z, xv.w};
#pragma unroll
            for (int n = 0; n < 4; n++)
#pragma unroll
                for (int m = 0; m < 4; m++) acc[n][m] += wa[n] * xa[m];
        }
    }
#pragma unroll
    for (int n = 0; n < 4; n++) {
        int o = oid * 4 + n;
        float bi = bias[o];
        float4 res;
        res.x = acc[n][0] + bi;
        res.y = acc[n][1] + bi;
        res.z = acc[n][2] + bi;
        res.w = acc[n][3] + bi;
        *(float4*)&out[(size_t)b * C8 * HW + (size_t)o * HW + hw0 + hid * 4] = res;
        Ts[hid * 4 + 0][o] = res.x;
        Ts[hid * 4 + 1][o] = res.y;
        Ts[hid * 4 + 2][o] = res.z;
        Ts[hid * 4 + 3][o] = res.w;
    }
    __syncthreads();
    // swizzled fp16 tile write
    {
        const int hw = tid >> 1, half = tid & 1;
        const size_t tb = ((size_t)(b * 32 + blockIdx.x)) * 8192;
        if (sel == 0) {
            char* dstb = (char*)g_qf + tb;
#pragma unroll
            for (int s = 0; s < 2; s++) {
                const int seg = half * 2 + s;
                uint32_t u[4];
#pragma unroll
                for (int e = 0; e < 4; e++)
                    u[e] = pack_h2(Ts[hw][seg * 8 + 2 * e], Ts[hw][seg * 8 + 2 * e + 1]);
                *(uint4*)(dstb + SWZ128((uint32_t)(hw * 64 + seg * 16))) =
                    make_uint4(u[0], u[1], u[2], u[3]);
            }
        } else {
            char* dh = (char*)g_kh2 + tb;
            char* dl = (char*)g_kl2 + tb;
#pragma unroll
            for (int s = 0; s < 2; s++) {
                const int seg = half * 2 + s;
                uint32_t uh[4], ul[4];
#pragma unroll
                for (int e = 0; e < 4; e++) {
                    float a = Ts[hw][seg * 8 + 2 * e];
                    float c = Ts[hw][seg * 8 + 2 * e + 1];
                    __half ha = __float2half_rn(a), hc = __float2half_rn(c);
                    __half la = __float2half_rn(a - __half2float(ha));
                    __half lc = __float2half_rn(c - __half2float(hc));
                    uh[e] = (uint32_t)*(uint16_t*)&ha | ((uint32_t)*(uint16_t*)&hc << 16);
                    ul[e] = (uint32_t)*(uint16_t*)&la | ((uint32_t)*(uint16_t*)&lc << 16);
                }
                uint32_t off = SWZ128((uint32_t)(hw * 64 + seg * 16));
                *(uint4*)(dh + off) = make_uint4(uh[0], uh[1], uh[2], uh[3]);
                *(uint4*)(dl + off) = make_uint4(ul[0], ul[1], ul[2], ul[3]);
            }
        }
    }
}

// ===================== v projection: fp16 2-term mma.sync ===================
__global__ __launch_bounds__(256) void v_mma(const float* __restrict__ X,
                                             const float* __restrict__ bias,
                                             float* __restrict__ vt) {
    extern __shared__ char dynsm[];
    const int tid  = threadIdx.x;
    const int lane = tid & 31;
    const int wid  = tid >> 5;
    const int wm   = wid & 3;
    const int wn   = wid >> 2;
    const int n0   = blockIdx.x * 128;
    const int m0   = blockIdx.y * 128;
    const int b    = blockIdx.z;

    const uint32_t smbase = smem_u32(dynsm);
    const uint32_t tB  = smbase;
    const uint32_t tAh = smbase + 16384;
    const uint32_t tAl = smbase + 32768;

    float acc[2][8][4];
#pragma unroll
    for (int mt = 0; mt < 2; mt++)
#pragma unroll
        for (int j = 0; j < 8; j++)
#pragma unroll
            for (int e = 0; e < 4; e++) acc[mt][j][e] = 0.f;

    const int arow  = wm * 32 + (lane & 15);
    const int acolh = (lane >> 4) * 16;
    const int brow  = wn * 64 + (lane & 7) + ((lane >> 4) << 3);
    const int bcolh = ((lane >> 3) & 1) * 16;
    const int c2    = tid >> 5;

    for (int s = 0; s < 4; s++) {
        const int kc = s * 64;
        __syncthreads();
#pragma unroll
        for (int i = 0; i < 8; i++) {
            const int t = i >> 2;
            const int c = ((i & 3) << 8) + tid;
            const int r = c >> 3, c16 = c & 7;
            uint32_t dst = (t ? tAl : tAh) + SWZ128((uint32_t)(r * 128 + c16 * 16));
            const __half* src = (t ? g_Wvl : g_Wvh) + (size_t)(m0 + r) * 256 + kc + c16 * 8;
            CP_ASYNC16(dst, src);
        }
        CP_COMMIT();
#pragma unroll
        for (int cc = 0; cc < 4; cc++) {
            const int cp = c2 + 8 * cc;
            const size_t row0 = ((size_t)b * Cc + kc + 2 * cp) * HW + n0;
#pragma unroll
            for (int pb = 0; pb < 4; pb++) {
                const int px = lane + 32 * pb;
                float v0 = X[row0 + px];
                float v1 = X[row0 + HW + px];
                uint32_t off = SWZ128((uint32_t)(px * 128 + cp * 4));
                *(uint32_t*)(dynsm + off) = pack_h2(v0, v1);
            }
        }
        CP_WAIT0();
        __syncthreads();

#pragma unroll
        for (int ks = 0; ks < 4; ks++) {
            uint32_t ah[2][4], al[2][4], bx[4][4];
#pragma unroll
            for (int mt = 0; mt < 2; mt++) {
                uint32_t off = SWZ128((uint32_t)((arow + mt * 16) * 128 + ks * 32 + acolh));
                ldsm_x4(ah[mt], tAh + off);
                ldsm_x4(al[mt], tAl + off);
            }
#pragma unroll
            for (int j = 0; j < 4; j++) {
                uint32_t off = SWZ128((uint32_t)((brow + j * 16) * 128 + ks * 32 + bcolh));
                ldsm_x4(bx[j], tB + off);
            }
#pragma unroll
            for (int mt = 0; mt < 2; mt++)
#pragma unroll
                for (int j = 0; j < 4; j++) {
                    mma_f16(acc[mt][2 * j],     ah[mt], bx[j][0], bx[j][1]);
                    mma_f16(acc[mt][2 * j + 1], ah[mt], bx[j][2], bx[j][3]);
                    mma_f16(acc[mt][2 * j],     al[mt], bx[j][0], bx[j][1]);
                    mma_f16(acc[mt][2 * j + 1], al[mt], bx[j][2], bx[j][3]);
                }
        }
    }

    __syncthreads();
    float* smep = (float*)dynsm;
#pragma unroll
    for (int mt = 0; mt < 2; mt++) {
        const int o_lo = wm * 32 + mt * 16 + (lane >> 2);
        const int o_hi = o_lo + 8;
        const float bi_lo = bias[m0 + o_lo], bi_hi = bias[m0 + o_hi];
#pragma unroll
        for (int j = 0; j < 8; j++) {
            const int p = wn * 64 + j * 8 + 2 * (lane & 3);
            smep[p * 132 + o_lo]       = acc[mt][j][0] + bi_lo;
            smep[(p + 1) * 132 + o_lo] = acc[mt][j][1] + bi_lo;
            smep[p * 132 + o_hi]       = acc[mt][j][2] + bi_hi;
            smep[(p + 1) * 132 + o_hi] = acc[mt][j][3] + bi_hi;
        }
    }
    __syncthreads();
#pragma unroll
    for (int r = 0; r < 16; r++) {
        const int p = wid + 8 * r;
        float4 v = *(const float4*)&smep[p * 132 + lane * 4];
        *(float4*)&vt[((size_t)b * HW + n0 + p) * Cc + m0 + lane * 4] = v;
    }
}

// ===================== tensor energy top-2 + certified argmax ===============
// CTA: 128 queries x 4096 keys (32 tiles). 8 warps = 4(key) x 2(query).
// smem: q 8KB | k 3 x 16KB | red 6KB. All tiles pre-swizzled (conflict-free).
#define EM_KBASE 8192
#define EM_RED (8192 + 49152)
#define EM_TOTAL (EM_RED + 6144)

__device__ __forceinline__ void em_stage_k(uint32_t smbase, int buf, int kt, int b) {
    const int tid = threadIdx.x;
    const size_t tb = ((size_t)(b * 32 + kt)) * 8192;
#pragma unroll
    for (int i = 0; i < 4; i++) {
        const int plane = i >> 1;
        const uint32_t off = tid * 16 + (i & 1) * 4096;
        const char* src = (const char*)(plane ? g_kl2 : g_kh2) + tb + off;
        CP_ASYNC16(smbase + EM_KBASE + buf * 16384 + plane * 8192 + off, src);
    }
    CP_COMMIT();
}

__global__ __launch_bounds__(256) void energy_mma() {
    extern __shared__ char dynsm[];
    const int tid  = threadIdx.x;
    const int lane = tid & 31;
    const int wid  = tid >> 5;
    const int wm   = wid & 3;
    const int wn   = wid >> 2;
    const int jt   = blockIdx.x;
    const int b    = blockIdx.y;

    const uint32_t smbase = smem_u32(dynsm);

    // stage q tile (8KB, linear copy of pre-swizzled tile)
    {
        const size_t tb = ((size_t)(b * 32 + jt)) * 8192;
#pragma unroll
        for (int i = 0; i < 2; i++) {
            const uint32_t off = tid * 16 + i * 4096;
            CP_ASYNC16(smbase + off, (const char*)g_qf + tb + off);
        }
    }
    em_stage_k(smbase, 0, 0, b);                 // group0 = q + k0
    em_stage_k(smbase, 1, 1, b);                 // group1 = k1

    float v1[16], v2[16];
    int   i1[16];
#pragma unroll
    for (int qs = 0; qs < 16; qs++) { v1[qs] = -FLT_MAX; v2[qs] = -FLT_MAX; i1[qs] = 0; }

    for (int kt = 0; kt < 32; kt++) {
        CP_WAIT1();
        __syncthreads();
        if (kt + 2 < 32) em_stage_k(smbase, (kt + 2) % 3, kt + 2, b);

        const uint32_t kb = smbase + EM_KBASE + (kt % 3) * 16384;
        float acc[2][8][4];
#pragma unroll
        for (int mt = 0; mt < 2; mt++)
#pragma unroll
            for (int jj = 0; jj < 8; jj++)
#pragma unroll
                for (int e = 0; e < 4; e++) acc[mt][jj][e] = 0.f;

#pragma unroll
        for (int ks = 0; ks < 2; ks++) {
            uint32_t kh_[2][4], kl_[2][4], qf_[4][4];
#pragma unroll
            for (int mt = 0; mt < 2; mt++) {
                uint32_t off = SWZ128((uint32_t)((wm * 32 + mt * 16 + (lane & 15)) * 64
                                                 + ks * 32 + ((lane >> 4) << 4)));
                ldsm_x4(kh_[mt], kb + off);
                ldsm_x4(kl_[mt], kb + 8192 + off);
            }
#pragma unroll
            for (int j = 0; j < 4; j++) {
                uint32_t off = SWZ128((uint32_t)((wn * 64 + (lane & 7) + ((lane >> 4) << 3)
                                                  + j * 16) * 64
                                                 + ks * 32 + (((lane >> 3) & 1) << 4)));
                ldsm_x4(qf_[j], smbase + off);
            }
#pragma unroll
            for (int mt = 0; mt < 2; mt++)
#pragma unroll
                for (int j = 0; j < 4; j++) {
                    mma_f16(acc[mt][2 * j],     kh_[mt], qf_[j][0], qf_[j][1]);
                    mma_f16(acc[mt][2 * j + 1], kh_[mt], qf_[j][2], qf_[j][3]);
                    mma_f16(acc[mt][2 * j],     kl_[mt], qf_[j][0], qf_[j][1]);
                    mma_f16(acc[mt][2 * j + 1], kl_[mt], qf_[j][2], qf_[j][3]);
                }
        }

        const int kbase = kt * 128 + wm * 32 + (lane >> 2);
#pragma unroll
        for (int mt = 0; mt < 2; mt++)
#pragma unroll
            for (int jj = 0; jj < 8; jj++)
#pragma unroll
                for (int e = 0; e < 4; e++) {
                    const float v = acc[mt][jj][e];
                    const int qs = jj * 2 + (e & 1);
                    if (v > v2[qs]) {
                        const int key = kbase + mt * 16 + ((e >> 1) << 3);
                        if (v > v1[qs]) { v2[qs] = v1[qs]; v1[qs] = v; i1[qs] = key; }
                        else v2[qs] = v;
                    }
                }
    }

    // reduce across the 8 threads per query column
#pragma unroll
    for (int qs = 0; qs < 16; qs++) {
#pragma unroll
        for (int st = 4; st <= 16; st <<= 1) {
            float ov1 = __shfl_xor_sync(0xffffffff, v1[qs], st);
            float ov2 = __shfl_xor_sync(0xffffffff, v2[qs], st);
            int   oi1 = __shfl_xor_sync(0xffffffff, i1[qs], st);
            float nv2 = fmaxf(fminf(v1[qs], ov1), fmaxf(v2[qs], ov2));
            if (ov1 > v1[qs]) { v1[qs] = ov1; i1[qs] = oi1; }
            v2[qs] = nv2;
        }
    }
    float* red = (float*)(dynsm + EM_RED);
    if (lane < 4) {
#pragma unroll
        for (int qs = 0; qs < 16; qs++) {
            const int col = (qs >> 1) * 8 + 2 * lane + (qs & 1);
            float* rp = red + ((wn * 64 + col) * 4 + wm) * 3;
            rp[0] = v1[qs];
            rp[1] = __int_as_float(i1[qs]);
            rp[2] = v2[qs];
        }
    }
    __syncthreads();
    if (tid < 128) {
        float* rp = red + tid * 12;
        float V1 = rp[0], V2 = rp[2];
        int   I1 = __float_as_int(rp[1]);
#pragma unroll
        for (int w = 1; w < 4; w++) {
            float a1 = rp[w * 3], a2 = rp[w * 3 + 2];
            int   ai = __float_as_int(rp[w * 3 + 1]);
            float nv2 = fmaxf(fminf(V1, a1), fmaxf(V2, a2));
            if (a1 > V1) { V1 = a1; I1 = ai; }
            V2 = nv2;
        }
        const int jq = jt * 128 + tid;
        g_arg[(size_t)b * HW + jq]  = I1;
        g_flag[(size_t)b * HW + jq] = (V1 - V2 < 4e-3f) ? 1 : 0;
    }
}

// exact fp32: full rescan for flagged queries; exact S for all (one warp/query)
__global__ __launch_bounds__(128) void recheck() {
    const int b = blockIdx.y;
    const int j = blockIdx.x * 4 + (threadIdx.x >> 5);
    const int lane = threadIdx.x & 31;

    if (g_flag[(size_t)b * HW + j]) {
        float qv[32];
#pragma unroll
        for (int c = 0; c < 32; c++) qv[c] = g_q[((size_t)b * C8 + c) * HW + j];
        float best = -FLT_MAX;
        int   bi = 0;
        for (int i = lane; i < HW; i += 32) {
            float e = 0.f;
#pragma unroll
            for (int c = 0; c < 32; c++)
                e = fmaf(g_k[((size_t)b * C8 + c) * HW + i], qv[c], e);
            if (e > best) { best = e; bi = i; }
        }
#pragma unroll
        for (int st = 16; st; st >>= 1) {
            float ov = __shfl_xor_sync(0xffffffff, best, st);
            int   oi = __shfl_xor_sync(0xffffffff, bi, st);
            if (ov > best || (ov == best && oi < bi)) { best = ov; bi = oi; }
        }
        if (lane == 0) {
            g_S[(size_t)b * HW + j]   = best;
            g_arg[(size_t)b * HW + j] = bi;
        }
    } else {
        const int a = g_arg[(size_t)b * HW + j];
        float e = g_k[((size_t)b * C8 + lane) * HW + a]
                * g_q[((size_t)b * C8 + lane) * HW + j];
#pragma unroll
        for (int st = 16; st; st >>= 1) e += __shfl_xor_sync(0xffffffff, e, st);
        if (lane == 0) g_S[(size_t)b * HW + j] = e;
    }
}

// ===================== conv input prep (fp16, single plane) =================
__global__ __launch_bounds__(256) void fill_xt(const float* __restrict__ front_x) {
    __shared__ float sm[32][65];
    const int c0 = blockIdx.x * 32;
    const int y  = blockIdx.y;
    const int b  = blockIdx.z;
    const int tid = threadIdx.x;
    const int x  = tid >> 2;
    const int g  = tid & 3;

    float vals[8];
    if (c0 < 256) {
#pragma unroll
        for (int pass = 0; pass < 8; pass++) {
            int idx = tid + pass * 256;
            int cc = idx >> 6, xx = idx & 63;
            sm[cc][xx] = front_x[((size_t)b * Cc + c0 + cc) * HW + y * Ww + xx];
        }
        __syncthreads();
#pragma unroll
        for (int e = 0; e < 8; e++) vals[e] = sm[g * 8 + e][x];
    } else {
        const int a = g_arg[b * HW + y * Ww + x];
        const float* vp = g_vt + ((size_t)b * HW + a) * Cc + (c0 - 256) + g * 8;
        float4 u0 = *(const float4*)vp;
        float4 u1 = *(const float4*)(vp + 4);
        vals[0] = u0.x; vals[1] = u0.y; vals[2] = u0.z; vals[3] = u0.w;
        vals[4] = u1.x; vals[5] = u1.y; vals[6] = u1.z; vals[7] = u1.w;
    }

    uint32_t hu[4];
#pragma unroll
    for (int e = 0; e < 4; e++) hu[e] = pack_h2(vals[e * 2], vals[e * 2 + 1]);
    size_t base = ((size_t)(b * 66 + y + 1) * 66 + (x + 1)) * 512 + c0 + g * 8;
    *(uint4*)&g_Xt[base] = make_uint4(hu[0], hu[1], hu[2], hu[3]);
}

__global__ void prep_w(const float* __restrict__ Wf) {
    int t = blockIdx.x * 256 + threadIdx.x;
    int o = t >> 9, i = t & 511;
#pragma unroll
    for (int k = 0; k < 9; k++) {
        float w = Wf[((size_t)o * 512 + i) * 9 + k];
        __half h = __float2half_rn(w);
        __half l = __float2half_rn(w - __half2float(h));
        g_Wa[(((size_t)0 * 9 + k) * 256 + o) * 512 + i] = h;
        g_Wa[(((size_t)1 * 9 + k) * 256 + o) * 512 + i] = l;
    }
}

__global__ void prep_wv(const float* __restrict__ Wv) {
    int t = blockIdx.x * 256 + threadIdx.x;
    float w = Wv[t];
    __half h = __float2half_rn(w);
    __half l = __float2half_rn(w - __half2float(h));
    g_Wvh[t] = h;
    g_Wvl[t] = l;
}

// ===================== mma.sync conv3x3 (fp16 2-term) + fused epilogue ======
#define STAGE 49152
#define NCHUNK 72

__device__ __forceinline__ void stage_chunk(uint32_t stg, int s, int b, int y0, int m0) {
    const int tap = s >> 3, kc = (s & 7) * 64;
    const int dy = tap / 3, dx = tap % 3;
    const int tid = threadIdx.x;
#pragma unroll
    for (int i = 0; i < 12; i++) {
        const int t = i >> 2;                          // 0:X 1:Wh 2:Wl
        const int u = ((i & 3) << 8) + tid;            // 0..1023
        const int r = u >> 3, c16 = u & 7;
        uint32_t dst = stg + (uint32_t)(t * 16384) + SWZ128((uint32_t)(r * 128 + c16 * 16));
        const void* src;
        if (t == 0) {
            const int ry = r >> 6, x = r & 63;
            src = &g_Xt[(((size_t)(b * 66 + y0 + ry + dy) * 66) + (x + dx)) * 512
                        + kc + c16 * 8];
        } else {
            src = &g_Wa[(((size_t)((t - 1) * 9 + tap) * 256) + m0 + r) * 512 + kc + c16 * 8];
        }
        CP_ASYNC16(dst, src);
    }
    CP_COMMIT();
}

__global__ __launch_bounds__(256, 1) void conv_mma(const float* __restrict__ front_x,
                                                   const float* __restrict__ bf,
                                                   float* __restrict__ out) {
    extern __shared__ char dynsm[];
    const int tid  = threadIdx.x;
    const int lane = tid & 31;
    const int wid  = tid >> 5;
    const int wm   = wid & 3;
    const int wn   = wid >> 2;
    const int nt   = blockIdx.x;
    const int m0   = blockIdx.y * 128;
    const int b    = blockIdx.z;
    const int y0   = nt * 2;
    const int n0   = nt * 128;

    const uint32_t smbase = smem_u32(dynsm);

    float acc[2][8][4];
#pragma unroll
    for (int mt = 0; mt < 2; mt++)
#pragma unroll
        for (int j = 0; j < 8; j++)
#pragma unroll
            for (int e = 0; e < 4; e++) acc[mt][j][e] = 0.f;

    const int arow  = wm * 32 + (lane & 15);
    const int acolh = (lane >> 4) * 16;
    const int brow  = wn * 64 + (lane & 7) + ((lane >> 4) << 3);
    const int bcolh = ((lane >> 3) & 1) * 16;

    stage_chunk(smbase,             0, b, y0, m0);
    stage_chunk(smbase + STAGE,     1, b, y0, m0);
    stage_chunk(smbase + 2 * STAGE, 2, b, y0, m0);

    for (int s = 0; s < NCHUNK; s++) {
        CP_WAIT2();
        __syncthreads();
        if (s + 3 < NCHUNK)
            stage_chunk(smbase + ((s + 3) & 3) * STAGE, s + 3, b, y0, m0);

        const uint32_t base = smbase + (s & 3) * STAGE;
        const uint32_t tB  = base;
        const uint32_t tAh = base + 16384;
        const uint32_t tAl = base + 32768;

#pragma unroll
        for (int ks = 0; ks < 4; ks++) {
            uint32_t ah[2][4], al[2][4], bx[4][4];
#pragma unroll
            for (int mt = 0; mt < 2; mt++) {
                uint32_t off = SWZ128((uint32_t)((arow + mt * 16) * 128 + ks * 32 + acolh));
                ldsm_x4(ah[mt], tAh + off);
                ldsm_x4(al[mt], tAl + off);
            }
#pragma unroll
            for (int j = 0; j < 4; j++) {
                uint32_t off = SWZ128((uint32_t)((brow + j * 16) * 128 + ks * 32 + bcolh));
                ldsm_x4(bx[j], tB + off);
            }
#pragma unroll
            for (int mt = 0; mt < 2; mt++)
#pragma unroll
                for (int j = 0; j < 4; j++) {
                    mma_f16(acc[mt][2 * j],     ah[mt], bx[j][0], bx[j][1]);
                    mma_f16(acc[mt][2 * j + 1], ah[mt], bx[j][2], bx[j][3]);
                    mma_f16(acc[mt][2 * j],     al[mt], bx[j][0], bx[j][1]);
                    mma_f16(acc[mt][2 * j + 1], al[mt], bx[j][2], bx[j][3]);
                }
        }
        __syncthreads();
    }

    const float* Sb = g_S + (size_t)b * HW;
#pragma unroll
    for (int mt = 0; mt < 2; mt++) {
        const int o_lo = m0 + wm * 32 + mt * 16 + (lane >> 2);
        const int o_hi = o_lo + 8;
        const float bi_lo = bf[o_lo], bi_hi = bf[o_hi];
#pragma unroll
        for (int j = 0; j < 8; j++) {
            const int p = n0 + wn * 64 + j * 8 + 2 * (lane & 3);
            const float2 Sv = *(const float2*)&Sb[p];
            const size_t off0 = ((size_t)(b * Cc + o_lo)) * HW + p;
            const size_t off1 = ((size_t)(b * Cc + o_hi)) * HW + p;
            const float2 f0 = *(const float2*)&front_x[off0];
            const float2 f1 = *(const float2*)&front_x[off1];
            float2 r0, r1;
            r0.x = f0.x + (acc[mt][j][0] + bi_lo) * Sv.x;
            r0.y = f0.y + (acc[mt][j][1] + bi_lo) * Sv.y;
            r1.x = f1.x + (acc[mt][j][2] + bi_hi) * Sv.x;
            r1.y = f1.y + (acc[mt][j][3] + bi_hi) * Sv.y;
            *(float2*)&out[off0] = r0;
            *(float2*)&out[off1] = r1;
        }
    }
}

// ===================== launch ==============================================
extern "C" void kernel_launch(void* const* d_in, const int* in_sizes, int n_in,
                              void* d_out, int out_size) {
    const float* front_x     = (const float*)d_in[0];
    const float* cross_x     = (const float*)d_in[1];
    const float* front_x_hat = (const float*)d_in[2];
    const float* Wq = (const float*)d_in[3];
    const float* bq = (const float*)d_in[4];
    const float* Wk = (const float*)d_in[5];
    const float* bk = (const float*)d_in[6];
    const float* Wv = (const float*)d_in[7];
    const float* bv = (const float*)d_in[8];
    const float* Wf = (const float*)d_in[9];
    const float* bf = (const float*)d_in[10];
    float* out = (float*)d_out;

    cudaFuncSetAttribute(conv_mma, cudaFuncAttributeMaxDynamicSharedMemorySize, 4 * STAGE);
    cudaFuncSetAttribute(v_mma, cudaFuncAttributeMaxDynamicSharedMemorySize, 128 * 132 * 4);
    cudaFuncSetAttribute(energy_mma, cudaFuncAttributeMaxDynamicSharedMemorySize, EM_TOTAL);

    float* vt;
    cudaGetSymbolAddress((void**)&vt, g_vt);

    prep_w<<<512, 256>>>(Wf);
    prep_wv<<<256, 256>>>(Wv);

    gemm_qk<<<dim3(32, 2, 4), 256>>>(cross_x, front_x, Wq, bq, Wk, bk);
    v_mma<<<dim3(32, 2, 4), 256, 128 * 132 * 4>>>(front_x_hat, bv, vt);

    energy_mma<<<dim3(32, 4), 256, EM_TOTAL>>>();
    recheck<<<dim3(1024, 4), 128>>>();

    fill_xt<<<dim3(16, 64, 4), 256>>>(front_x);

    conv_mma<<<dim3(32, 2, 4), 256, 4 * STAGE>>>(front_x, bf, out);
}

// round 11
// speedup vs baseline: 1.3004x; 1.3004x over previous
#include <cuda_runtime.h>
#include <cuda_fp16.h>
#include <float.h>
#include <stdint.h>

#define Bb 4
#define Cc 256
#define C8 32
#define Hh 64
#define Ww 64
#define HW 4096

// ===================== helpers =============================================
__device__ __forceinline__ uint32_t smem_u32(const void* p) {
    uint32_t a;
    asm("{ .reg .u64 t; cvta.to.shared.u64 t, %1; cvt.u32.u64 %0, t; }"
        : "=r"(a) : "l"(p));
    return a;
}
#define SWZ128(off) ((off) ^ (((off) >> 3) & 0x70))

__device__ __forceinline__ void ldsm_x4(uint32_t (&r)[4], uint32_t addr) {
    asm volatile("ldmatrix.sync.aligned.m8n8.x4.shared.b16 {%0,%1,%2,%3}, [%4];"
                 : "=r"(r[0]), "=r"(r[1]), "=r"(r[2]), "=r"(r[3]) : "r"(addr));
}

__device__ __forceinline__ void mma_f16(float (&d)[4], const uint32_t (&a)[4],
                                        uint32_t b0, uint32_t b1) {
    asm volatile(
        "mma.sync.aligned.m16n8k16.row.col.f32.f16.f16.f32 "
        "{%0,%1,%2,%3}, {%4,%5,%6,%7}, {%8,%9}, {%0,%1,%2,%3};"
        : "+f"(d[0]), "+f"(d[1]), "+f"(d[2]), "+f"(d[3])
        : "r"(a[0]), "r"(a[1]), "r"(a[2]), "r"(a[3]), "r"(b0), "r"(b1));
}

#define CP_ASYNC16(dst, src) \
    asm volatile("cp.async.cg.shared.global [%0], [%1], 16;" :: "r"(dst), "l"(src) : "memory")
#define CP_COMMIT()  asm volatile("cp.async.commit_group;" ::: "memory")
#define CP_WAIT2()   asm volatile("cp.async.wait_group 2;" ::: "memory")
#define CP_WAIT0()   asm volatile("cp.async.wait_group 0;" ::: "memory")

__device__ __forceinline__ uint32_t pack_h2(float a, float b) {
    __half2 h = __floats2half2_rn(a, b);
    return *(uint32_t*)&h;
}

// ===================== scratch =============================================
__device__ float g_q[Bb * C8 * HW];
__device__ float g_k[Bb * C8 * HW];
__device__ float g_vt[Bb * HW * Cc];          // NHWC value: [b][p][c]
__device__ float g_pmax[Bb * 4 * HW];
__device__ int   g_parg[Bb * 4 * HW];
__device__ float g_S[Bb * HW];
__device__ int   g_arg[Bb * HW];
// NHWC fp16 single plane, zero halo (device globals zero-init; halo never written)
__device__ __half g_Xt[(size_t)Bb * 66 * 66 * 512];
// conv weights fp16 single plane: [tap9][o 256][c 512]
__device__ __half g_Wa[9 * 256 * 512];
// v weights fp16 single plane: [o 256][c 256]
__device__ __half g_Wv16[256 * 256];

// ===================== fused q+k projection (exact fp32) ====================
__global__ __launch_bounds__(256) void gemm_qk(const float* __restrict__ cross_x,
                                               const float* __restrict__ front_x,
                                               const float* __restrict__ Wq,
                                               const float* __restrict__ bq,
                                               const float* __restrict__ Wk,
                                               const float* __restrict__ bk) {
    __shared__ float Xs[16][128];
    __shared__ float Ws[16][36];
    const int b   = blockIdx.z;
    const int sel = blockIdx.y;                 // 0 -> q, 1 -> k
    const int hw0 = blockIdx.x * 128;
    const int tid = threadIdx.x;
    const int hid = tid & 31;
    const int oid = tid >> 5;

    const float* X    = sel ? front_x : cross_x;
    const float* Wm   = sel ? Wk : Wq;
    const float* bias = sel ? bk : bq;
    float*       out  = sel ? g_k : g_q;

    const float* xb = X + (size_t)b * Cc * HW;
    float acc[4][4];
#pragma unroll
    for (int n = 0; n < 4; n++)
#pragma unroll
        for (int m = 0; m < 4; m++) acc[n][m] = 0.f;

    for (int c0 = 0; c0 < Cc; c0 += 16) {
        __syncthreads();
#pragma unroll
        for (int r = 0; r < 8; r++) {
            int idx = tid + r * 256;
            int cc = idx >> 7, h = idx & 127;
            Xs[cc][h] = xb[(size_t)(c0 + cc) * HW + hw0 + h];
        }
#pragma unroll
        for (int r = 0; r < 2; r++) {
            int idx = tid + r * 256;
            int cc = idx >> 5, o = idx & 31;
            Ws[cc][o] = Wm[(size_t)o * Cc + c0 + cc];
        }
        __syncthreads();
#pragma unroll
        for (int cc = 0; cc < 16; cc++) {
            float4 wv = *(const float4*)&Ws[cc][oid * 4];
            float4 xv = *(const float4*)&Xs[cc][hid * 4];
            float wa[4] = {wv.x, wv.y, wv.z, wv.w};
            float xa[4] = {xv.x, xv.y, xv.z, xv.w};
#pragma unroll
            for (int n = 0; n < 4; n++)
#pragma unroll
                for (int m = 0; m < 4; m++) acc[n][m] += wa[n] * xa[m];
        }
    }
#pragma unroll
    for (int n = 0; n < 4; n++) {
        int o = oid * 4 + n;
        float bi = bias[o];
        float4 res;
        res.x = acc[n][0] + bi;
        res.y = acc[n][1] + bi;
        res.z = acc[n][2] + bi;
        res.w = acc[n][3] + bi;
        *(float4*)&out[(size_t)b * C8 * HW + (size_t)o * HW + hw0 + hid * 4] = res;
    }
}

// ===================== v projection: fp16 single-term mma.sync ==============
__global__ __launch_bounds__(256) void v_mma(const float* __restrict__ X,
                                             const float* __restrict__ bias,
                                             float* __restrict__ vt) {
    extern __shared__ char dynsm[];
    const int tid  = threadIdx.x;
    const int lane = tid & 31;
    const int wid  = tid >> 5;
    const int wm   = wid & 3;
    const int wn   = wid >> 2;
    const int n0   = blockIdx.x * 128;
    const int m0   = blockIdx.y * 128;
    const int b    = blockIdx.z;

    const uint32_t smbase = smem_u32(dynsm);
    const uint32_t tB = smbase;
    const uint32_t tA = smbase + 16384;

    float acc[2][8][4];
#pragma unroll
    for (int mt = 0; mt < 2; mt++)
#pragma unroll
        for (int j = 0; j < 8; j++)
#pragma unroll
            for (int e = 0; e < 4; e++) acc[mt][j][e] = 0.f;

    const int arow  = wm * 32 + (lane & 15);
    const int acolh = (lane >> 4) * 16;
    const int brow  = wn * 64 + (lane & 7) + ((lane >> 4) << 3);
    const int bcolh = ((lane >> 3) & 1) * 16;
    const int c2    = tid >> 5;

    for (int s = 0; s < 4; s++) {
        const int kc = s * 64;
        __syncthreads();
        // A tile (Wv fp16) via cp.async: 16KB
#pragma unroll
        for (int i = 0; i < 4; i++) {
            const int c = (i << 8) + tid;
            const int r = c >> 3, c16 = c & 7;
            uint32_t dst = tA + SWZ128((uint32_t)(r * 128 + c16 * 16));
            const __half* src = g_Wv16 + (size_t)(m0 + r) * 256 + kc + c16 * 8;
            CP_ASYNC16(dst, src);
        }
        CP_COMMIT();
        // B tile: LDG fp32 -> fp16 -> STS [px][ch]
#pragma unroll
        for (int cc = 0; cc < 4; cc++) {
            const int cp = c2 + 8 * cc;
            const size_t row0 = ((size_t)b * Cc + kc + 2 * cp) * HW + n0;
#pragma unroll
            for (int pb = 0; pb < 4; pb++) {
                const int px = lane + 32 * pb;
                float v0 = X[row0 + px];
                float v1 = X[row0 + HW + px];
                uint32_t off = SWZ128((uint32_t)(px * 128 + cp * 4));
                *(uint32_t*)(dynsm + off) = pack_h2(v0, v1);
            }
        }
        CP_WAIT0();
        __syncthreads();

#pragma unroll
        for (int ks = 0; ks < 4; ks++) {
            uint32_t ax[2][4], bx[4][4];
#pragma unroll
            for (int mt = 0; mt < 2; mt++) {
                uint32_t off = SWZ128((uint32_t)((arow + mt * 16) * 128 + ks * 32 + acolh));
                ldsm_x4(ax[mt], tA + off);
            }
#pragma unroll
            for (int j = 0; j < 4; j++) {
                uint32_t off = SWZ128((uint32_t)((brow + j * 16) * 128 + ks * 32 + bcolh));
                ldsm_x4(bx[j], tB + off);
            }
#pragma unroll
            for (int mt = 0; mt < 2; mt++)
#pragma unroll
                for (int j = 0; j < 4; j++) {
                    mma_f16(acc[mt][2 * j],     ax[mt], bx[j][0], bx[j][1]);
                    mma_f16(acc[mt][2 * j + 1], ax[mt], bx[j][2], bx[j][3]);
                }
        }
    }

    // epilogue: transpose through padded smem (row stride 132 floats)
    __syncthreads();
    float* smep = (float*)dynsm;
#pragma unroll
    for (int mt = 0; mt < 2; mt++) {
        const int o_lo = wm * 32 + mt * 16 + (lane >> 2);
        const int o_hi = o_lo + 8;
        const float bi_lo = bias[m0 + o_lo], bi_hi = bias[m0 + o_hi];
#pragma unroll
        for (int j = 0; j < 8; j++) {
            const int p = wn * 64 + j * 8 + 2 * (lane & 3);
            smep[p * 132 + o_lo]       = acc[mt][j][0] + bi_lo;
            smep[(p + 1) * 132 + o_lo] = acc[mt][j][1] + bi_lo;
            smep[p * 132 + o_hi]       = acc[mt][j][2] + bi_hi;
            smep[(p + 1) * 132 + o_hi] = acc[mt][j][3] + bi_hi;
        }
    }
    __syncthreads();
#pragma unroll
    for (int r = 0; r < 16; r++) {
        const int p = wid + 8 * r;
        float4 v = *(const float4*)&smep[p * 132 + lane * 4];
        *(float4*)&vt[((size_t)b * HW + n0 + p) * Cc + m0 + lane * 4] = v;
    }
}

// ===================== energy rowmax/argmax (exact fp32) ====================
__global__ __launch_bounds__(128) void energy_argmax() {
    __shared__ float ks[32][128];
    const int b  = blockIdx.y;
    const int j  = blockIdx.x * 128 + threadIdx.x;
    const int sp = blockIdx.z;
    const float* qb = g_q + (size_t)b * C8 * HW;
    const float* kb = g_k + (size_t)b * C8 * HW;

    float qr[32];
#pragma unroll
    for (int c = 0; c < 32; c++) qr[c] = qb[c * HW + j];

    float best = -FLT_MAX;
    int   barg = 0;
    const int i0base = sp * 1024;

    for (int it = 0; it < 8; it++) {
        int i0 = i0base + it * 128;
        __syncthreads();
#pragma unroll
        for (int c = 0; c < 32; c++) ks[c][threadIdx.x] = kb[c * HW + i0 + threadIdx.x];
        __syncthreads();
#pragma unroll 4
        for (int ii = 0; ii < 128; ii += 4) {
            float a0 = 0.f, a1 = 0.f, a2 = 0.f, a3 = 0.f;
#pragma unroll
            for (int c = 0; c < 32; c++) {
                float4 kv = *(const float4*)&ks[c][ii];
                a0 += kv.x * qr[c];
                a1 += kv.y * qr[c];
                a2 += kv.z * qr[c];
                a3 += kv.w * qr[c];
            }
            if (a0 > best) { best = a0; barg = i0 + ii; }
            if (a1 > best) { best = a1; barg = i0 + ii + 1; }
            if (a2 > best) { best = a2; barg = i0 + ii + 2; }
            if (a3 > best) { best = a3; barg = i0 + ii + 3; }
        }
    }
    g_pmax[((size_t)b * 4 + sp) * HW + j] = best;
    g_parg[((size_t)b * 4 + sp) * HW + j] = barg;
}

__global__ void reduce_argmax() {
    int t = blockIdx.x * 256 + threadIdx.x;
    if (t >= Bb * HW) return;
    int b = t >> 12, j = t & 4095;
    float best = g_pmax[((size_t)b * 4) * HW + j];
    int   arg  = g_parg[((size_t)b * 4) * HW + j];
#pragma unroll
    for (int sp = 1; sp < 4; sp++) {
        float e = g_pmax[((size_t)b * 4 + sp) * HW + j];
        if (e > best) { best = e; arg = g_parg[((size_t)b * 4 + sp) * HW + j]; }
    }
    g_S[t] = best;
    g_arg[t] = arg;
}

// ===================== conv input prep (fp16, single plane) =================
__global__ __launch_bounds__(256) void fill_xt(const float* __restrict__ front_x) {
    __shared__ float sm[32][65];
    const int c0 = blockIdx.x * 32;
    const int y  = blockIdx.y;
    const int b  = blockIdx.z;
    const int tid = threadIdx.x;
    const int x  = tid >> 2;
    const int g  = tid & 3;

    float vals[8];
    if (c0 < 256) {
#pragma unroll
        for (int pass = 0; pass < 8; pass++) {
            int idx = tid + pass * 256;
            int cc = idx >> 6, xx = idx & 63;
            sm[cc][xx] = front_x[((size_t)b * Cc + c0 + cc) * HW + y * Ww + xx];
        }
        __syncthreads();
#pragma unroll
        for (int e = 0; e < 8; e++) vals[e] = sm[g * 8 + e][x];
    } else {
        const int a = g_arg[b * HW + y * Ww + x];
        const float* vp = g_vt + ((size_t)b * HW + a) * Cc + (c0 - 256) + g * 8;
        float4 u0 = *(const float4*)vp;
        float4 u1 = *(const float4*)(vp + 4);
        vals[0] = u0.x; vals[1] = u0.y; vals[2] = u0.z; vals[3] = u0.w;
        vals[4] = u1.x; vals[5] = u1.y; vals[6] = u1.z; vals[7] = u1.w;
    }

    uint32_t hu[4];
#pragma unroll
    for (int e = 0; e < 4; e++) hu[e] = pack_h2(vals[e * 2], vals[e * 2 + 1]);
    size_t base = ((size_t)(b * 66 + y + 1) * 66 + (x + 1)) * 512 + c0 + g * 8;
    *(uint4*)&g_Xt[base] = make_uint4(hu[0], hu[1], hu[2], hu[3]);
}

// conv weights: Wf(O=256, I=512, 3,3) -> g_Wa[tap][o][i] fp16
__global__ void prep_w(const float* __restrict__ Wf) {
    int t = blockIdx.x * 256 + threadIdx.x;
    int o = t >> 9, i = t & 511;
#pragma unroll
    for (int k = 0; k < 9; k++) {
        float w = Wf[((size_t)o * 512 + i) * 9 + k];
        g_Wa[(((size_t)k) * 256 + o) * 512 + i] = __float2half_rn(w);
    }
}

__global__ void prep_wv(const float* __restrict__ Wv) {
    int t = blockIdx.x * 256 + threadIdx.x;
    g_Wv16[t] = __float2half_rn(Wv[t]);
}

// ===================== mma.sync conv3x3 (fp16 single-term) + epilogue =======
// CTA: M=128 out-ch x N=128 px. K: 9 taps x 8 chunks of 64ch.
// Stage/chunk: 2 SW128 tiles of 128x64 fp16 (X, W; 16KB each),
// cp.async 4-stage pipeline (32KB/stage).
#define STAGE 32768
#define NCHUNK 72

__device__ __forceinline__ void stage_chunk(uint32_t stg, int s, int b, int y0, int m0) {
    const int tap = s >> 3, kc = (s & 7) * 64;
    const int dy = tap / 3, dx = tap % 3;
    const int tid = threadIdx.x;
#pragma unroll
    for (int i = 0; i < 8; i++) {
        const int t = i >> 2;                          // 0:X 1:W
        const int u = ((i & 3) << 8) + tid;            // 0..1023
        const int r = u >> 3, c16 = u & 7;
        uint32_t dst = stg + (uint32_t)(t * 16384) + SWZ128((uint32_t)(r * 128 + c16 * 16));
        const void* src;
        if (t == 0) {
            const int ry = r >> 6, x = r & 63;
            src = &g_Xt[(((size_t)(b * 66 + y0 + ry + dy) * 66) + (x + dx)) * 512
                        + kc + c16 * 8];
        } else {
            src = &g_Wa[(((size_t)tap * 256) + m0 + r) * 512 + kc + c16 * 8];
        }
        CP_ASYNC16(dst, src);
    }
    CP_COMMIT();
}

__global__ __launch_bounds__(256, 1) void conv_mma(const float* __restrict__ front_x,
                                                   const float* __restrict__ bf,
                                                   float* __restrict__ out) {
    extern __shared__ char dynsm[];
    const int tid  = threadIdx.x;
    const int lane = tid & 31;
    const int wid  = tid >> 5;
    const int wm   = wid & 3;
    const int wn   = wid >> 2;
    const int nt   = blockIdx.x;
    const int m0   = blockIdx.y * 128;
    const int b    = blockIdx.z;
    const int y0   = nt * 2;
    const int n0   = nt * 128;

    const uint32_t smbase = smem_u32(dynsm);

    float acc[2][8][4];
#pragma unroll
    for (int mt = 0; mt < 2; mt++)
#pragma unroll
        for (int j = 0; j < 8; j++)
#pragma unroll
            for (int e = 0; e < 4; e++) acc[mt][j][e] = 0.f;

    const int arow  = wm * 32 + (lane & 15);
    const int acolh = (lane >> 4) * 16;
    const int brow  = wn * 64 + (lane & 7) + ((lane >> 4) << 3);
    const int bcolh = ((lane >> 3) & 1) * 16;

    stage_chunk(smbase,             0, b, y0, m0);
    stage_chunk(smbase + STAGE,     1, b, y0, m0);
    stage_chunk(smbase + 2 * STAGE, 2, b, y0, m0);

    for (int s = 0; s < NCHUNK; s++) {
        CP_WAIT2();
        __syncthreads();
        if (s + 3 < NCHUNK)
            stage_chunk(smbase + ((s + 3) & 3) * STAGE, s + 3, b, y0, m0);

        const uint32_t base = smbase + (s & 3) * STAGE;
        const uint32_t tB = base;
        const uint32_t tA = base + 16384;

#pragma unroll
        for (int ks = 0; ks < 4; ks++) {
            uint32_t ax[2][4], bx[4][4];
#pragma unroll
            for (int mt = 0; mt < 2; mt++) {
                uint32_t off = SWZ128((uint32_t)((arow + mt * 16) * 128 + ks * 32 + acolh));
                ldsm_x4(ax[mt], tA + off);
            }
#pragma unroll
            for (int j = 0; j < 4; j++) {
                uint32_t off = SWZ128((uint32_t)((brow + j * 16) * 128 + ks * 32 + bcolh));
                ldsm_x4(bx[j], tB + off);
            }
#pragma unroll
            for (int mt = 0; mt < 2; mt++)
#pragma unroll
                for (int j = 0; j < 4; j++) {
                    mma_f16(acc[mt][2 * j],     ax[mt], bx[j][0], bx[j][1]);
                    mma_f16(acc[mt][2 * j + 1], ax[mt], bx[j][2], bx[j][3]);
                }
        }
        __syncthreads();
    }

    // fused epilogue: out = front_x + (conv + bf) * S
    const float* Sb = g_S + (size_t)b * HW;
#pragma unroll
    for (int mt = 0; mt < 2; mt++) {
        const int o_lo = m0 + wm * 32 + mt * 16 + (lane >> 2);
        const int o_hi = o_lo + 8;
        const float bi_lo = bf[o_lo], bi_hi = bf[o_hi];
#pragma unroll
        for (int j = 0; j < 8; j++) {
            const int p = n0 + wn * 64 + j * 8 + 2 * (lane & 3);
            const float2 Sv = *(const float2*)&Sb[p];
            const size_t off0 = ((size_t)(b * Cc + o_lo)) * HW + p;
            const size_t off1 = ((size_t)(b * Cc + o_hi)) * HW + p;
            const float2 f0 = *(const float2*)&front_x[off0];
            const float2 f1 = *(const float2*)&front_x[off1];
            float2 r0, r1;
            r0.x = f0.x + (acc[mt][j][0] + bi_lo) * Sv.x;
            r0.y = f0.y + (acc[mt][j][1] + bi_lo) * Sv.y;
            r1.x = f1.x + (acc[mt][j][2] + bi_hi) * Sv.x;
            r1.y = f1.y + (acc[mt][j][3] + bi_hi) * Sv.y;
            *(float2*)&out[off0] = r0;
            *(float2*)&out[off1] = r1;
        }
    }
}

// ===================== launch ==============================================
extern "C" void kernel_launch(void* const* d_in, const int* in_sizes, int n_in,
                              void* d_out, int out_size) {
    const float* front_x     = (const float*)d_in[0];
    const float* cross_x     = (const float*)d_in[1];
    const float* front_x_hat = (const float*)d_in[2];
    const float* Wq = (const float*)d_in[3];
    const float* bq = (const float*)d_in[4];
    const float* Wk = (const float*)d_in[5];
    const float* bk = (const float*)d_in[6];
    const float* Wv = (const float*)d_in[7];
    const float* bv = (const float*)d_in[8];
    const float* Wf = (const float*)d_in[9];
    const float* bf = (const float*)d_in[10];
    float* out = (float*)d_out;

    cudaFuncSetAttribute(conv_mma, cudaFuncAttributeMaxDynamicSharedMemorySize, 4 * STAGE);
    cudaFuncSetAttribute(v_mma, cudaFuncAttributeMaxDynamicSharedMemorySize, 128 * 132 * 4);

    float* vt;
    cudaGetSymbolAddress((void**)&vt, g_vt);

    prep_w<<<512, 256>>>(Wf);
    prep_wv<<<256, 256>>>(Wv);

    gemm_qk<<<dim3(32, 2, 4), 256>>>(cross_x, front_x, Wq, bq, Wk, bk);
    v_mma<<<dim3(32, 2, 4), 256, 128 * 132 * 4>>>(front_x_hat, bv, vt);

    energy_argmax<<<dim3(32, 4, 4), 128>>>();
    reduce_argmax<<<64, 256>>>();

    fill_xt<<<dim3(16, 64, 4), 256>>>(front_x);

    conv_mma<<<dim3(32, 2, 4), 256, 4 * STAGE>>>(front_x, bf, out);
}

// round 12
// speedup vs baseline: 1.3027x; 1.0018x over previous
#include <cuda_runtime.h>
#include <cuda_fp16.h>
#include <float.h>
#include <stdint.h>

#define Bb 4
#define Cc 256
#define C8 32
#define Hh 64
#define Ww 64
#define HW 4096

// ===================== helpers =============================================
__device__ __forceinline__ uint32_t smem_u32(const void* p) {
    uint32_t a;
    asm("{ .reg .u64 t; cvta.to.shared.u64 t, %1; cvt.u32.u64 %0, t; }"
        : "=r"(a) : "l"(p));
    return a;
}
#define SWZ128(off) ((off) ^ (((off) >> 3) & 0x70))

__device__ __forceinline__ void ldsm_x4(uint32_t (&r)[4], uint32_t addr) {
    asm volatile("ldmatrix.sync.aligned.m8n8.x4.shared.b16 {%0,%1,%2,%3}, [%4];"
                 : "=r"(r[0]), "=r"(r[1]), "=r"(r[2]), "=r"(r[3]) : "r"(addr));
}

__device__ __forceinline__ void mma_f16(float (&d)[4], const uint32_t (&a)[4],
                                        uint32_t b0, uint32_t b1) {
    asm volatile(
        "mma.sync.aligned.m16n8k16.row.col.f32.f16.f16.f32 "
        "{%0,%1,%2,%3}, {%4,%5,%6,%7}, {%8,%9}, {%0,%1,%2,%3};"
        : "+f"(d[0]), "+f"(d[1]), "+f"(d[2]), "+f"(d[3])
        : "r"(a[0]), "r"(a[1]), "r"(a[2]), "r"(a[3]), "r"(b0), "r"(b1));
}

#define CP_ASYNC16(dst, src) \
    asm volatile("cp.async.cg.shared.global [%0], [%1], 16;" :: "r"(dst), "l"(src) : "memory")
#define CP_COMMIT()  asm volatile("cp.async.commit_group;" ::: "memory")
#define CP_WAIT2()   asm volatile("cp.async.wait_group 2;" ::: "memory")
#define CP_WAIT0()   asm volatile("cp.async.wait_group 0;" ::: "memory")

__device__ __forceinline__ uint32_t pack_h2(float a, float b) {
    __half2 h = __floats2half2_rn(a, b);
    return *(uint32_t*)&h;
}

// ===================== scratch =============================================
__device__ float g_q[Bb * C8 * HW];
__device__ float g_k[Bb * C8 * HW];
__device__ float g_vt[Bb * HW * Cc];          // NHWC value: [b][p][c]
__device__ float g_pmax[Bb * 4 * HW];
__device__ int   g_parg[Bb * 4 * HW];
__device__ float g_S[Bb * HW];
__device__ int   g_arg[Bb * HW];
// NHWC fp16 single plane, zero halo (device globals zero-init; halo never written)
__device__ __half g_Xt[(size_t)Bb * 66 * 66 * 512];
// conv weights fp16 single plane: [tap9][o 256][c 512]
__device__ __half g_Wa[9 * 256 * 512];
// v weights fp16 single plane: [o 256][c 256]
__device__ __half g_Wv16[256 * 256];

// ===================== fused q+k projection (exact fp32) ====================
__global__ __launch_bounds__(256) void gemm_qk(const float* __restrict__ cross_x,
                                               const float* __restrict__ front_x,
                                               const float* __restrict__ Wq,
                                               const float* __restrict__ bq,
                                               const float* __restrict__ Wk,
                                               const float* __restrict__ bk) {
    __shared__ float Xs[16][128];
    __shared__ float Ws[16][36];
    const int b   = blockIdx.z;
    const int sel = blockIdx.y;                 // 0 -> q, 1 -> k
    const int hw0 = blockIdx.x * 128;
    const int tid = threadIdx.x;
    const int hid = tid & 31;
    const int oid = tid >> 5;

    const float* X    = sel ? front_x : cross_x;
    const float* Wm   = sel ? Wk : Wq;
    const float* bias = sel ? bk : bq;
    float*       out  = sel ? g_k : g_q;

    const float* xb = X + (size_t)b * Cc * HW;
    float acc[4][4];
#pragma unroll
    for (int n = 0; n < 4; n++)
#pragma unroll
        for (int m = 0; m < 4; m++) acc[n][m] = 0.f;

    for (int c0 = 0; c0 < Cc; c0 += 16) {
        __syncthreads();
#pragma unroll
        for (int r = 0; r < 8; r++) {
            int idx = tid + r * 256;
            int cc = idx >> 7, h = idx & 127;
            Xs[cc][h] = xb[(size_t)(c0 + cc) * HW + hw0 + h];
        }
#pragma unroll
        for (int r = 0; r < 2; r++) {
            int idx = tid + r * 256;
            int cc = idx >> 5, o = idx & 31;
            Ws[cc][o] = Wm[(size_t)o * Cc + c0 + cc];
        }
        __syncthreads();
#pragma unroll
        for (int cc = 0; cc < 16; cc++) {
            float4 wv = *(const float4*)&Ws[cc][oid * 4];
            float4 xv = *(const float4*)&Xs[cc][hid * 4];
            float wa[4] = {wv.x, wv.y, wv.z, wv.w};
            float xa[4] = {xv.x, xv.y, xv.z, xv.w};
#pragma unroll
            for (int n = 0; n < 4; n++)
#pragma unroll
                for (int m = 0; m < 4; m++) acc[n][m] += wa[n] * xa[m];
        }
    }
#pragma unroll
    for (int n = 0; n < 4; n++) {
        int o = oid * 4 + n;
        float bi = bias[o];
        float4 res;
        res.x = acc[n][0] + bi;
        res.y = acc[n][1] + bi;
        res.z = acc[n][2] + bi;
        res.w = acc[n][3] + bi;
        *(float4*)&out[(size_t)b * C8 * HW + (size_t)o * HW + hw0 + hid * 4] = res;
    }
}

// ===================== fused mid kernel =====================================
// blockIdx.x ranges (long blocks first):
//   [0,256)      energy rowmax/argmax (exact fp32), 256 queries/CTA
//   [256,512)    v projection (fp16 mma.sync)
//   [512,2560)   fill g_Xt front channels (fp16)
//   [2560,3072)  prep conv weights (fp16)
#define SEG_EN  256
#define SEG_VM  512
#define SEG_FI  2560
#define SEG_PW  3072
#define MID_SMEM 67584

__global__ __launch_bounds__(256) void mid_fused(const float* __restrict__ front_x,
                                                 const float* __restrict__ Xhat,
                                                 const float* __restrict__ bv,
                                                 const float* __restrict__ Wf) {
    extern __shared__ char dynsm[];
    const int tid  = threadIdx.x;
    const int bid  = blockIdx.x;

    if (bid < SEG_EN) {
        // ---------------- energy rowmax/argmax (exact fp32) ----------------
        float* ks = (float*)dynsm;                    // [32][128]
        const int jt = bid & 15;
        const int sp = (bid >> 4) & 3;
        const int b  = bid >> 6;
        const int j  = jt * 256 + tid;
        const float* qb = g_q + (size_t)b * C8 * HW;
        const float* kb = g_k + (size_t)b * C8 * HW;

        float qr[32];
#pragma unroll
        for (int c = 0; c < 32; c++) qr[c] = qb[c * HW + j];

        float best = -FLT_MAX;
        int   barg = 0;
        const int i0base = sp * 1024;

        for (int it = 0; it < 8; it++) {
            int i0 = i0base + it * 128;
            __syncthreads();
#pragma unroll
            for (int p = 0; p < 16; p++) {
                int idx = tid + p * 256;
                int cc = idx >> 7, h = idx & 127;
                ks[cc * 128 + h] = kb[cc * HW + i0 + h];
            }
            __syncthreads();
#pragma unroll 4
            for (int ii = 0; ii < 128; ii += 4) {
                float a0 = 0.f, a1 = 0.f, a2 = 0.f, a3 = 0.f;
#pragma unroll
                for (int c = 0; c < 32; c++) {
                    float4 kv = *(const float4*)&ks[c * 128 + ii];
                    a0 += kv.x * qr[c];
                    a1 += kv.y * qr[c];
                    a2 += kv.z * qr[c];
                    a3 += kv.w * qr[c];
                }
                if (a0 > best) { best = a0; barg = i0 + ii; }
                if (a1 > best) { best = a1; barg = i0 + ii + 1; }
                if (a2 > best) { best = a2; barg = i0 + ii + 2; }
                if (a3 > best) { best = a3; barg = i0 + ii + 3; }
            }
        }
        g_pmax[((size_t)b * 4 + sp) * HW + j] = best;
        g_parg[((size_t)b * 4 + sp) * HW + j] = barg;

    } else if (bid < SEG_VM) {
        // ---------------- v projection: fp16 mma.sync -----------------------
        const int id   = bid - SEG_EN;
        const int lane = tid & 31;
        const int wid  = tid >> 5;
        const int wm   = wid & 3;
        const int wn   = wid >> 2;
        const int n0   = (id & 31) * 128;
        const int m0   = ((id >> 5) & 1) * 128;
        const int b    = id >> 6;

        const uint32_t smbase = smem_u32(dynsm);
        const uint32_t tB = smbase;
        const uint32_t tA = smbase + 16384;

        float acc[2][8][4];
#pragma unroll
        for (int mt = 0; mt < 2; mt++)
#pragma unroll
            for (int j = 0; j < 8; j++)
#pragma unroll
                for (int e = 0; e < 4; e++) acc[mt][j][e] = 0.f;

        const int arow  = wm * 32 + (lane & 15);
        const int acolh = (lane >> 4) * 16;
        const int brow  = wn * 64 + (lane & 7) + ((lane >> 4) << 3);
        const int bcolh = ((lane >> 3) & 1) * 16;
        const int c2    = tid >> 5;

        for (int s = 0; s < 4; s++) {
            const int kc = s * 64;
            __syncthreads();
#pragma unroll
            for (int i = 0; i < 4; i++) {
                const int c = (i << 8) + tid;
                const int r = c >> 3, c16 = c & 7;
                uint32_t dst = tA + SWZ128((uint32_t)(r * 128 + c16 * 16));
                const __half* src = g_Wv16 + (size_t)(m0 + r) * 256 + kc + c16 * 8;
                CP_ASYNC16(dst, src);
            }
            CP_COMMIT();
#pragma unroll
            for (int cc = 0; cc < 4; cc++) {
                const int cp = c2 + 8 * cc;
                const size_t row0 = ((size_t)b * Cc + kc + 2 * cp) * HW + n0;
#pragma unroll
                for (int pb = 0; pb < 4; pb++) {
                    const int px = lane + 32 * pb;
                    float v0 = Xhat[row0 + px];
                    float v1 = Xhat[row0 + HW + px];
                    uint32_t off = SWZ128((uint32_t)(px * 128 + cp * 4));
                    *(uint32_t*)(dynsm + off) = pack_h2(v0, v1);
                }
            }
            CP_WAIT0();
            __syncthreads();

#pragma unroll
            for (int ks2 = 0; ks2 < 4; ks2++) {
                uint32_t ax[2][4], bx[4][4];
#pragma unroll
                for (int mt = 0; mt < 2; mt++) {
                    uint32_t off = SWZ128((uint32_t)((arow + mt * 16) * 128 + ks2 * 32 + acolh));
                    ldsm_x4(ax[mt], tA + off);
                }
#pragma unroll
                for (int j = 0; j < 4; j++) {
                    uint32_t off = SWZ128((uint32_t)((brow + j * 16) * 128 + ks2 * 32 + bcolh));
                    ldsm_x4(bx[j], tB + off);
                }
#pragma unroll
                for (int mt = 0; mt < 2; mt++)
#pragma unroll
                    for (int j = 0; j < 4; j++) {
                        mma_f16(acc[mt][2 * j],     ax[mt], bx[j][0], bx[j][1]);
                        mma_f16(acc[mt][2 * j + 1], ax[mt], bx[j][2], bx[j][3]);
                    }
            }
        }

        __syncthreads();
        float* smep = (float*)dynsm;
#pragma unroll
        for (int mt = 0; mt < 2; mt++) {
            const int o_lo = wm * 32 + mt * 16 + (lane >> 2);
            const int o_hi = o_lo + 8;
            const float bi_lo = bv[m0 + o_lo], bi_hi = bv[m0 + o_hi];
#pragma unroll
            for (int j = 0; j < 8; j++) {
                const int p = wn * 64 + j * 8 + 2 * (lane & 3);
                smep[p * 132 + o_lo]       = acc[mt][j][0] + bi_lo;
                smep[(p + 1) * 132 + o_lo] = acc[mt][j][1] + bi_lo;
                smep[p * 132 + o_hi]       = acc[mt][j][2] + bi_hi;
                smep[(p + 1) * 132 + o_hi] = acc[mt][j][3] + bi_hi;
            }
        }
        __syncthreads();
#pragma unroll
        for (int r = 0; r < 16; r++) {
            const int p = wid + 8 * r;
            float4 v = *(const float4*)&smep[p * 132 + lane * 4];
            *(float4*)&g_vt[((size_t)b * HW + n0 + p) * Cc + m0 + lane * 4] = v;
        }

    } else if (bid < SEG_FI) {
        // ---------------- fill g_Xt front channels (fp16) -------------------
        float* sm = (float*)dynsm;                    // [32][65]
        const int id = bid - SEG_VM;
        const int c0 = (id & 7) * 32;
        const int y  = (id >> 3) & 63;
        const int b  = id >> 9;
        const int x  = tid >> 2;
        const int g  = tid & 3;

#pragma unroll
        for (int pass = 0; pass < 8; pass++) {
            int idx = tid + pass * 256;
            int cc = idx >> 6, xx = idx & 63;
            sm[cc * 65 + xx] = front_x[((size_t)b * Cc + c0 + cc) * HW + y * Ww + xx];
        }
        __syncthreads();
        uint32_t hu[4];
#pragma unroll
        for (int e = 0; e < 4; e++)
            hu[e] = pack_h2(sm[(g * 8 + 2 * e) * 65 + x], sm[(g * 8 + 2 * e + 1) * 65 + x]);
        size_t base = ((size_t)(b * 66 + y + 1) * 66 + (x + 1)) * 512 + c0 + g * 8;
        *(uint4*)&g_Xt[base] = make_uint4(hu[0], hu[1], hu[2], hu[3]);

    } else {
        // ---------------- prep conv weights (fp16) --------------------------
        const int t = (bid - SEG_FI) * 256 + tid;     // < 131072
        const int o = t >> 9, i = t & 511;
#pragma unroll
        for (int k = 0; k < 9; k++) {
            float w = Wf[((size_t)o * 512 + i) * 9 + k];
            g_Wa[(((size_t)k) * 256 + o) * 512 + i] = __float2half_rn(w);
        }
    }
}

// ===================== reduce + fill T half =================================
__global__ void reduce_argmax() {
    int t = blockIdx.x * 256 + threadIdx.x;
    if (t >= Bb * HW) return;
    int b = t >> 12, j = t & 4095;
    float best = g_pmax[((size_t)b * 4) * HW + j];
    int   arg  = g_parg[((size_t)b * 4) * HW + j];
#pragma unroll
    for (int sp = 1; sp < 4; sp++) {
        float e = g_pmax[((size_t)b * 4 + sp) * HW + j];
        if (e > best) { best = e; arg = g_parg[((size_t)b * 4 + sp) * HW + j]; }
    }
    g_S[t] = best;
    g_arg[t] = arg;
}

__global__ __launch_bounds__(256) void fill_xt_T() {
    const int c0 = 256 + blockIdx.x * 32;
    const int y  = blockIdx.y;
    const int b  = blockIdx.z;
    const int tid = threadIdx.x;
    const int x  = tid >> 2;
    const int g  = tid & 3;

    const int a = g_arg[b * HW + y * Ww + x];
    const float* vp = g_vt + ((size_t)b * HW + a) * Cc + (c0 - 256) + g * 8;
    float4 u0 = *(const float4*)vp;
    float4 u1 = *(const float4*)(vp + 4);

    uint32_t hu[4];
    hu[0] = pack_h2(u0.x, u0.y);
    hu[1] = pack_h2(u0.z, u0.w);
    hu[2] = pack_h2(u1.x, u1.y);
    hu[3] = pack_h2(u1.z, u1.w);
    size_t base = ((size_t)(b * 66 + y + 1) * 66 + (x + 1)) * 512 + c0 + g * 8;
    *(uint4*)&g_Xt[base] = make_uint4(hu[0], hu[1], hu[2], hu[3]);
}

__global__ void prep_wv(const float* __restrict__ Wv) {
    int t = blockIdx.x * 256 + threadIdx.x;
    g_Wv16[t] = __float2half_rn(Wv[t]);
}

// ===================== mma.sync conv3x3 (fp16 single-term) + epilogue =======
#define STAGE 32768
#define NCHUNK 72

__device__ __forceinline__ void stage_chunk(uint32_t stg, int s, int b, int y0, int m0) {
    const int tap = s >> 3, kc = (s & 7) * 64;
    const int dy = tap / 3, dx = tap % 3;
    const int tid = threadIdx.x;
#pragma unroll
    for (int i = 0; i < 8; i++) {
        const int t = i >> 2;                          // 0:X 1:W
        const int u = ((i & 3) << 8) + tid;            // 0..1023
        const int r = u >> 3, c16 = u & 7;
        uint32_t dst = stg + (uint32_t)(t * 16384) + SWZ128((uint32_t)(r * 128 + c16 * 16));
        const void* src;
        if (t == 0) {
            const int ry = r >> 6, x = r & 63;
            src = &g_Xt[(((size_t)(b * 66 + y0 + ry + dy) * 66) + (x + dx)) * 512
                        + kc + c16 * 8];
        } else {
            src = &g_Wa[(((size_t)tap * 256) + m0 + r) * 512 + kc + c16 * 8];
        }
        CP_ASYNC16(dst, src);
    }
    CP_COMMIT();
}

__global__ __launch_bounds__(256, 1) void conv_mma(const float* __restrict__ front_x,
                                                   const float* __restrict__ bf,
                                                   float* __restrict__ out) {
    extern __shared__ char dynsm[];
    const int tid  = threadIdx.x;
    const int lane = tid & 31;
    const int wid  = tid >> 5;
    const int wm   = wid & 3;
    const int wn   = wid >> 2;
    const int nt   = blockIdx.x;
    const int m0   = blockIdx.y * 128;
    const int b    = blockIdx.z;
    const int y0   = nt * 2;
    const int n0   = nt * 128;

    const uint32_t smbase = smem_u32(dynsm);

    float acc[2][8][4];
#pragma unroll
    for (int mt = 0; mt < 2; mt++)
#pragma unroll
        for (int j = 0; j < 8; j++)
#pragma unroll
            for (int e = 0; e < 4; e++) acc[mt][j][e] = 0.f;

    const int arow  = wm * 32 + (lane & 15);
    const int acolh = (lane >> 4) * 16;
    const int brow  = wn * 64 + (lane & 7) + ((lane >> 4) << 3);
    const int bcolh = ((lane >> 3) & 1) * 16;

    stage_chunk(smbase,             0, b, y0, m0);
    stage_chunk(smbase + STAGE,     1, b, y0, m0);
    stage_chunk(smbase + 2 * STAGE, 2, b, y0, m0);

    for (int s = 0; s < NCHUNK; s++) {
        CP_WAIT2();
        __syncthreads();
        if (s + 3 < NCHUNK)
            stage_chunk(smbase + ((s + 3) & 3) * STAGE, s + 3, b, y0, m0);

        const uint32_t base = smbase + (s & 3) * STAGE;
        const uint32_t tB = base;
        const uint32_t tA = base + 16384;

#pragma unroll
        for (int ks = 0; ks < 4; ks++) {
            uint32_t ax[2][4], bx[4][4];
#pragma unroll
            for (int mt = 0; mt < 2; mt++) {
                uint32_t off = SWZ128((uint32_t)((arow + mt * 16) * 128 + ks * 32 + acolh));
                ldsm_x4(ax[mt], tA + off);
            }
#pragma unroll
            for (int j = 0; j < 4; j++) {
                uint32_t off = SWZ128((uint32_t)((brow + j * 16) * 128 + ks * 32 + bcolh));
                ldsm_x4(bx[j], tB + off);
            }
#pragma unroll
            for (int mt = 0; mt < 2; mt++)
#pragma unroll
                for (int j = 0; j < 4; j++) {
                    mma_f16(acc[mt][2 * j],     ax[mt], bx[j][0], bx[j][1]);
                    mma_f16(acc[mt][2 * j + 1], ax[mt], bx[j][2], bx[j][3]);
                }
        }
        __syncthreads();
    }

    const float* Sb = g_S + (size_t)b * HW;
#pragma unroll
    for (int mt = 0; mt < 2; mt++) {
        const int o_lo = m0 + wm * 32 + mt * 16 + (lane >> 2);
        const int o_hi = o_lo + 8;
        const float bi_lo = bf[o_lo], bi_hi = bf[o_hi];
#pragma unroll
        for (int j = 0; j < 8; j++) {
            const int p = n0 + wn * 64 + j * 8 + 2 * (lane & 3);
            const float2 Sv = *(const float2*)&Sb[p];
            const size_t off0 = ((size_t)(b * Cc + o_lo)) * HW + p;
            const size_t off1 = ((size_t)(b * Cc + o_hi)) * HW + p;
            const float2 f0 = *(const float2*)&front_x[off0];
            const float2 f1 = *(const float2*)&front_x[off1];
            float2 r0, r1;
            r0.x = f0.x + (acc[mt][j][0] + bi_lo) * Sv.x;
            r0.y = f0.y + (acc[mt][j][1] + bi_lo) * Sv.y;
            r1.x = f1.x + (acc[mt][j][2] + bi_hi) * Sv.x;
            r1.y = f1.y + (acc[mt][j][3] + bi_hi) * Sv.y;
            *(float2*)&out[off0] = r0;
            *(float2*)&out[off1] = r1;
        }
    }
}

// ===================== launch ==============================================
extern "C" void kernel_launch(void* const* d_in, const int* in_sizes, int n_in,
                              void* d_out, int out_size) {
    const float* front_x     = (const float*)d_in[0];
    const float* cross_x     = (const float*)d_in[1];
    const float* front_x_hat = (const float*)d_in[2];
    const float* Wq = (const float*)d_in[3];
    const float* bq = (const float*)d_in[4];
    const float* Wk = (const float*)d_in[5];
    const float* bk = (const float*)d_in[6];
    const float* Wv = (const float*)d_in[7];
    const float* bv = (const float*)d_in[8];
    const float* Wf = (const float*)d_in[9];
    const float* bf = (const float*)d_in[10];
    float* out = (float*)d_out;

    cudaFuncSetAttribute(conv_mma, cudaFuncAttributeMaxDynamicSharedMemorySize, 4 * STAGE);
    cudaFuncSetAttribute(mid_fused, cudaFuncAttributeMaxDynamicSharedMemorySize, MID_SMEM);

    prep_wv<<<256, 256>>>(Wv);

    gemm_qk<<<dim3(32, 2, 4), 256>>>(cross_x, front_x, Wq, bq, Wk, bk);

    mid_fused<<<SEG_PW, 256, MID_SMEM>>>(front_x, front_x_hat, bv, Wf);

    reduce_argmax<<<64, 256>>>();
    fill_xt_T<<<dim3(8, 64, 4), 256>>>();

    conv_mma<<<dim3(32, 2, 4), 256, 4 * STAGE>>>(front_x, bf, out);
}